// round 12
// baseline (speedup 1.0000x reference)
#include <cuda_runtime.h>
#include <cuda_fp16.h>
#include <cstdint>
#include <cstddef>

// ============================================================
// Problem constants
// ============================================================
#define N_TOK 8192
#define OUT_F 4096
#define IN_F  4096
#define NBITS 8
#define STEPF 0.0078125f

// GEMM tiling: 1 CTA/SM, 64x64 warp tile, BK=128, 2-stage ring
#define BM 128
#define BN 256
#define BK 128
#define KTILES (IN_F / BK)      // 32
#define GTHREADS 256

// Stage layout (96KB): A sub0 16KB | A sub1 16KB | B sub0 32KB | B sub1 32KB
#define OFF_A0 0
#define OFF_A1 16384
#define OFF_B0 32768
#define OFF_B1 65536
#define STAGE_BYTES 98304
#define SMEM_TOTAL  (2 * STAGE_BYTES)   // 196608

// ============================================================
// Device scratch (allocation-free rule: __device__ globals)
// ============================================================
__device__ __align__(16) __half g_X[(size_t)N_TOK * IN_F];   // 64 MB
__device__ __align__(16) __half g_W[(size_t)OUT_F * IN_F];   // 32 MB

// ============================================================
// Helpers
// ============================================================
__device__ __forceinline__ uint32_t smem_u32(const void* p) {
    uint32_t a;
    asm("{ .reg .u64 t; cvta.to.shared.u64 t, %1; cvt.u32.u64 %0, t; }"
        : "=r"(a) : "l"(p));
    return a;
}

__device__ __forceinline__ void cp_async16(uint32_t saddr, const void* gaddr) {
    asm volatile("cp.async.cg.shared.global [%0], [%1], 16;"
                 :: "r"(saddr), "l"(gaddr));
}

__device__ __forceinline__ void ldmatrix_x4(uint32_t& r0, uint32_t& r1,
                                            uint32_t& r2, uint32_t& r3,
                                            uint32_t addr) {
    asm volatile("ldmatrix.sync.aligned.m8n8.x4.shared.b16 {%0,%1,%2,%3}, [%4];"
                 : "=r"(r0), "=r"(r1), "=r"(r2), "=r"(r3) : "r"(addr));
}

__device__ __forceinline__ void mma_16816(float& d0, float& d1, float& d2, float& d3,
                                          uint32_t a0, uint32_t a1, uint32_t a2, uint32_t a3,
                                          uint32_t b0, uint32_t b1) {
    asm volatile(
        "mma.sync.aligned.m16n8k16.row.col.f32.f16.f16.f32 "
        "{%0,%1,%2,%3}, {%4,%5,%6,%7}, {%8,%9}, {%0,%1,%2,%3};"
        : "+f"(d0), "+f"(d1), "+f"(d2), "+f"(d3)
        : "r"(a0), "r"(a1), "r"(a2), "r"(a3), "r"(b0), "r"(b1));
}

__device__ __forceinline__ uint32_t pack_h2(float a, float b) {
    __half2 h = __floats2half2_rn(a, b);
    return *reinterpret_cast<uint32_t*>(&h);
}

// ============================================================
// Fused prep kernel, 8 elements/thread for MLP.
//   blocks [0, WBLOCKS8): W reconstruction (8 weights, 256B read, 16B write)
//   blocks [WBLOCKS8, +XBLOCKS8): X fp32->fp16 (8 floats, 32B read, 16B write)
// ============================================================
#define WBLOCKS8 8192    // (OUT_F*IN_F/8) / 256
#define XBLOCKS8 16384   // (N_TOK*IN_F/8) / 256

__global__ void prep_kernel(const float* __restrict__ x,
                            const float* __restrict__ w_twos,
                            const float* __restrict__ base) {
    if (blockIdx.x < WBLOCKS8) {
        size_t q = (size_t)blockIdx.x * blockDim.x + threadIdx.x;  // 8-elem group

        const float4 bs0 = __ldg(reinterpret_cast<const float4*>(base));
        const float4 bs1 = __ldg(reinterpret_cast<const float4*>(base) + 1);

        const float4* src = reinterpret_cast<const float4*>(w_twos + q * 8 * NBITS);
        float o[8];
#pragma unroll
        for (int e = 0; e < 8; ++e) {
            float4 u0 = src[e * 2];
            float4 u1 = src[e * 2 + 1];
            o[e] = (u0.x * bs0.x + u0.y * bs0.y + u0.z * bs0.z + u0.w * bs0.w +
                    u1.x * bs1.x + u1.y * bs1.y + u1.z * bs1.z + u1.w * bs1.w) * STEPF;
        }
        uint4 pk;
        pk.x = pack_h2(o[0], o[1]);
        pk.y = pack_h2(o[2], o[3]);
        pk.z = pack_h2(o[4], o[5]);
        pk.w = pack_h2(o[6], o[7]);
        reinterpret_cast<uint4*>(g_W)[q] = pk;
    } else {
        size_t i = (size_t)(blockIdx.x - WBLOCKS8) * blockDim.x + threadIdx.x;
        const float4* xs = reinterpret_cast<const float4*>(x) + i * 2;
        float4 v0 = xs[0];
        float4 v1 = xs[1];
        uint4 pk;
        pk.x = pack_h2(v0.x, v0.y);
        pk.y = pack_h2(v0.z, v0.w);
        pk.z = pack_h2(v1.x, v1.y);
        pk.w = pack_h2(v1.z, v1.w);
        reinterpret_cast<uint4*>(g_X)[i] = pk;
    }
}

// ============================================================
// fp16 mma.sync GEMM  out[m,n] = sum_k X[m,k]*W[n,k] + b[n]
// BM=128, BN=256, BK=128, 8 warps (2m x 4n, warp tile 64x64),
// 2-stage ring (96KB each), barrier every 8 ks steps, drip-fed
// cp.async, wait hoisted to ks5, cross-tile ks0 prefetch.
// ============================================================
__global__ __launch_bounds__(GTHREADS, 1)
void gemm_kernel(const float* __restrict__ bias, float* __restrict__ out) {
    extern __shared__ char sm[];
    const uint32_t smem_base = smem_u32(sm);
    const int tid  = threadIdx.x;
    const int wid  = tid >> 5;
    const int lane = tid & 31;
    const int warp_m = wid & 1;    // 64 rows each
    const int warp_n = wid >> 1;   // 0..3, 64 cols each
    const int m0 = blockIdx.y * BM;
    const int n0 = blockIdx.x * BN;

    // ---- per-lane ldmatrix addressing (within a 64-col subtile) ----
    uint32_t a_row[4], a_xor[4];
#pragma unroll
    for (int im = 0; im < 4; ++im) {
        int r = warp_m * 64 + im * 16 + (lane & 15);
        a_row[im] = (uint32_t)(r * 128);
        a_xor[im] = (uint32_t)((r & 7) * 16);
    }
    const uint32_t a_khb = (uint32_t)((lane >> 4) * 16);

    uint32_t b_row[4], b_xor[4];
#pragma unroll
    for (int jp = 0; jp < 4; ++jp) {
        int r = warp_n * 64 + jp * 16 + ((lane >> 4) * 8) + (lane & 7);
        b_row[jp] = (uint32_t)(r * 128);
        b_xor[jp] = (uint32_t)((r & 7) * 16);
    }
    const uint32_t b_khb = (uint32_t)(((lane >> 3) & 1) * 16);

    // ---- cp.async lane assignments (per 64-col subtile) ----
    uint32_t a_soff[4];  const __half* a_gp[4];
    uint32_t b_soff[8];  const __half* b_gp[8];
#pragma unroll
    for (int i = 0; i < 4; ++i) {
        int id = tid + i * 256;
        int r = id >> 3, c = id & 7;
        a_soff[i] = (uint32_t)(r * 128 + ((c * 16) ^ ((r & 7) * 16)));
        a_gp[i] = g_X + (size_t)(m0 + r) * IN_F + c * 8;
    }
#pragma unroll
    for (int i = 0; i < 8; ++i) {
        int id = tid + i * 256;
        int r = id >> 3, c = id & 7;
        b_soff[i] = (uint32_t)(r * 128 + ((c * 16) ^ ((r & 7) * 16)));
        b_gp[i] = g_W + (size_t)(n0 + r) * IN_F + c * 8;
    }

    float acc[4][8][4];   // 128 regs: warp tile 64x64
#pragma unroll
    for (int im = 0; im < 4; ++im)
#pragma unroll
        for (int jn = 0; jn < 8; ++jn)
#pragma unroll
            for (int q = 0; q < 4; ++q) acc[im][jn][q] = 0.0f;

    // ---- prologue: load tile 0 into stage 0 ----
    {
        uint32_t sb = smem_base;
#pragma unroll
        for (int i = 0; i < 4; ++i) {
            cp_async16(sb + OFF_A0 + a_soff[i], a_gp[i]);
            cp_async16(sb + OFF_A1 + a_soff[i], a_gp[i] + 64);
        }
#pragma unroll
        for (int i = 0; i < 8; ++i) {
            cp_async16(sb + OFF_B0 + b_soff[i], b_gp[i]);
            cp_async16(sb + OFF_B1 + b_soff[i], b_gp[i] + 64);
        }
        asm volatile("cp.async.commit_group;");
    }
    asm volatile("cp.async.wait_group 0;");
    __syncthreads();

    uint32_t a[4][4];   // single-buffer fragments
    uint32_t b[8][2];

    // prefetch ks0 frags of tile 0
    {
        uint32_t sS = smem_base;
#pragma unroll
        for (int im = 0; im < 4; ++im)
            ldmatrix_x4(a[im][0], a[im][1], a[im][2], a[im][3],
                        sS + OFF_A0 + a_row[im] + (a_khb ^ a_xor[im]));
#pragma unroll
        for (int jp = 0; jp < 4; ++jp)
            ldmatrix_x4(b[2 * jp][0], b[2 * jp][1],
                        b[2 * jp + 1][0], b[2 * jp + 1][1],
                        sS + OFF_B0 + b_row[jp] + (b_khb ^ b_xor[jp]));
    }

    // ---- main loop: 32 K-tiles, barrier only at tile tail ----
    for (int kt = 0; kt < KTILES; ++kt) {
        const uint32_t sS = smem_base + (kt & 1) * STAGE_BYTES;
        const uint32_t sb = smem_base + ((kt + 1) & 1) * STAGE_BYTES;
        const int ktn = kt + 1;
        const int kof = ktn * BK;

#pragma unroll
        for (int ks = 0; ks < 8; ++ks) {
            // frag loads for this ks (ks0 was prefetched across the barrier)
            if (ks > 0) {
                const uint32_t aoff = (ks & 4) ? OFF_A1 : OFF_A0;
                const uint32_t boff = (ks & 4) ? OFF_B1 : OFF_B0;
                const uint32_t k32 = (uint32_t)((ks & 3) * 32);
#pragma unroll
                for (int im = 0; im < 4; ++im)
                    ldmatrix_x4(a[im][0], a[im][1], a[im][2], a[im][3],
                                sS + aoff + a_row[im] + ((k32 + a_khb) ^ a_xor[im]));
#pragma unroll
                for (int jp = 0; jp < 4; ++jp)
                    ldmatrix_x4(b[2 * jp][0], b[2 * jp][1],
                                b[2 * jp + 1][0], b[2 * jp + 1][1],
                                sS + boff + b_row[jp] + ((k32 + b_khb) ^ b_xor[jp]));
            }
#pragma unroll
            for (int im = 0; im < 4; ++im)
#pragma unroll
                for (int jn = 0; jn < 8; ++jn)
                    mma_16816(acc[im][jn][0], acc[im][jn][1],
                              acc[im][jn][2], acc[im][jn][3],
                              a[im][0], a[im][1], a[im][2], a[im][3],
                              b[jn][0], b[jn][1]);

            // drip-feed next tile's copies under the tensor work
            if (ktn < KTILES) {
                if (ks == 0) {
#pragma unroll
                    for (int i = 0; i < 4; ++i)
                        cp_async16(sb + OFF_A0 + a_soff[i], a_gp[i] + kof);
                } else if (ks == 1) {
#pragma unroll
                    for (int i = 0; i < 8; ++i)
                        cp_async16(sb + OFF_B0 + b_soff[i], b_gp[i] + kof);
                } else if (ks == 2) {
#pragma unroll
                    for (int i = 0; i < 4; ++i)
                        cp_async16(sb + OFF_A1 + a_soff[i], a_gp[i] + kof + 64);
                } else if (ks == 3) {
#pragma unroll
                    for (int i = 0; i < 8; ++i)
                        cp_async16(sb + OFF_B1 + b_soff[i], b_gp[i] + kof + 64);
                    asm volatile("cp.async.commit_group;");
                }
            }
            // wait hoisted off the tail: group committed at ks3 has had
            // ~2 ks-steps to land; tail becomes a bare __syncthreads.
            if (ks == 5) {
                asm volatile("cp.async.wait_group 0;");
            }
        }

        // tail rendezvous: publish stage sb, release stage sS for overwrite
        __syncthreads();

        // cross-tile prefetch: ks0 frags of tile kt+1 from the other stage
        if (ktn < KTILES) {
#pragma unroll
            for (int im = 0; im < 4; ++im)
                ldmatrix_x4(a[im][0], a[im][1], a[im][2], a[im][3],
                            sb + OFF_A0 + a_row[im] + (a_khb ^ a_xor[im]));
#pragma unroll
            for (int jp = 0; jp < 4; ++jp)
                ldmatrix_x4(b[2 * jp][0], b[2 * jp][1],
                            b[2 * jp + 1][0], b[2 * jp + 1][1],
                            sb + OFF_B0 + b_row[jp] + (b_khb ^ b_xor[jp]));
        }
    }

    // ---- epilogue: bias + store ----
#pragma unroll
    for (int im = 0; im < 4; ++im) {
        int r0 = m0 + warp_m * 64 + im * 16 + (lane >> 2);
        int r1 = r0 + 8;
#pragma unroll
        for (int jn = 0; jn < 8; ++jn) {
            int c = n0 + warp_n * 64 + jn * 8 + (lane & 3) * 2;
            float2 bv = *reinterpret_cast<const float2*>(bias + c);
            float2 o0, o1;
            o0.x = acc[im][jn][0] + bv.x;
            o0.y = acc[im][jn][1] + bv.y;
            o1.x = acc[im][jn][2] + bv.x;
            o1.y = acc[im][jn][3] + bv.y;
            *reinterpret_cast<float2*>(out + (size_t)r0 * OUT_F + c) = o0;
            *reinterpret_cast<float2*>(out + (size_t)r1 * OUT_F + c) = o1;
        }
    }
}

// ============================================================
// Host launcher
// ============================================================
extern "C" void kernel_launch(void* const* d_in, const int* in_sizes, int n_in,
                              void* d_out, int out_size) {
    const float* x      = (const float*)d_in[0];
    const float* w_twos = (const float*)d_in[1];
    const float* b      = (const float*)d_in[2];
    const float* base   = (const float*)d_in[3];
    float* out = (float*)d_out;

    cudaFuncSetAttribute(gemm_kernel,
                         cudaFuncAttributeMaxDynamicSharedMemorySize, SMEM_TOTAL);

    prep_kernel<<<WBLOCKS8 + XBLOCKS8, 256>>>(x, w_twos, base);

    dim3 grid(OUT_F / BN, N_TOK / BM);
    gemm_kernel<<<grid, GTHREADS, SMEM_TOTAL>>>(b, out);
}